// round 11
// baseline (speedup 1.0000x reference)
#include <cuda_runtime.h>
#include <cuda_bf16.h>
#include <math.h>

// ---------------------------------------------------------------------------
// MAD_4612794876398  (round 10)
//  lenet_kernel : R2 conv core, byte-identical (proven 232 us). Queries store
//                 400-float features; refs store 12-float Wf projections.
//  proj_kernel  : dual-query f32x2 GEMM for the 132 Wg/Wf projection rows.
//  combine_kernel: R3-proven tiny combine (~11 us).
//  2 dummy launches pad the per-call launch count to 5 so ncu's "-s 5 -c 1"
//  lands on lenet_kernel (profiling alignment; ~1-2 us cost).
// ---------------------------------------------------------------------------

#define FEAT   400
#define HID    12
#define NCLS   10
#define SMAX   8
#define NQ_MAX 1024
#define NR_MAX (NQ_MAX * SMAX)
#define BDIM   224      // lenet block
#define QPB    4        // combine queries per block
#define PPB    4        // proj query-pairs per block (8 queries)

__device__ float g_feat[NQ_MAX * FEAT];       // query features
__device__ float g_x[NQ_MAX * HID];           // query Wf projections
__device__ float g_grad[NQ_MAX * HID * NCLS]; // query Wg projections
__device__ float g_rx[NR_MAX * HID];          // ref Wf projections

typedef unsigned long long ull;

__device__ __forceinline__ ull pack2(float lo, float hi) {
    ull r; asm("mov.b64 %0, {%1, %2};" : "=l"(r) : "f"(lo), "f"(hi)); return r;
}
__device__ __forceinline__ void unpack2(ull v, float& lo, float& hi) {
    asm("mov.b64 {%0, %1}, %2;" : "=f"(lo), "=f"(hi) : "l"(v));
}
__device__ __forceinline__ ull fma2(ull a, ull b, ull c) {
    ull d; asm("fma.rn.f32x2 %0, %1, %2, %3;" : "=l"(d) : "l"(a), "l"(b), "l"(c));
    return d;
}
__device__ __forceinline__ ull ld64(const float2* p) {
    return *reinterpret_cast<const ull*>(p);
}

// ---------------------------------------------------------------------------
// LeNet feature kernel: one block per image  (== round 2, unchanged)
// ---------------------------------------------------------------------------
__global__ __launch_bounds__(BDIM, 3)
void lenet_kernel(const float* __restrict__ img,
                  const float* __restrict__ train,
                  const int*   __restrict__ refs,
                  const float* __restrict__ w1, const float* __restrict__ b1,
                  const float* __restrict__ w2, const float* __restrict__ b2,
                  const float* __restrict__ Wf, const float* __restrict__ bf,
                  int n_img)
{
    __shared__ float  s_img[3][32][32];
    __shared__ float2 s_wp1[3][25][3];
    __shared__ float2 s_wp2[6][25][8];
    __shared__ float  s_b1[6];
    __shared__ float  s_b2[16];
    __shared__ float  s_p1[6][14][14];
    __shared__ float  s_feat[FEAT];

    const int b = blockIdx.x;
    const int t = threadIdx.x;

    const float* src = (b < n_img)
        ? img + (size_t)b * 3072
        : train + (size_t)refs[b - n_img] * 3072;

    {
        const float4* s4 = reinterpret_cast<const float4*>(src);
        float4* d4 = reinterpret_cast<float4*>(&s_img[0][0][0]);
        for (int i = t; i < 768; i += BDIM) d4[i] = s4[i];
    }
    for (int i = t; i < 225; i += BDIM) {
        int ic = i / 75, r = i % 75, k = r / 3, j = r % 3;
        s_wp1[ic][k][j] = make_float2(w1[(2*j)     * 75 + ic * 25 + k],
                                      w1[(2*j + 1) * 75 + ic * 25 + k]);
    }
    for (int i = t; i < 1200; i += BDIM) {
        int ic = i / 200, r = i % 200, k = r / 8, j = r % 8;
        s_wp2[ic][k][j] = make_float2(w2[(2*j)     * 150 + ic * 25 + k],
                                      w2[(2*j + 1) * 150 + ic * 25 + k]);
    }
    if (t < 6)  s_b1[t] = b1[t];
    if (t < 16) s_b2[t] = b2[t];
    __syncthreads();

    if (t < 196) {
        const int py = t / 14, px = t % 14;
        const int iy = 2 * py, ix = 2 * px;

        ull acc[3][4];
        #pragma unroll
        for (int j = 0; j < 3; j++) {
            ull bz = pack2(s_b1[2*j], s_b1[2*j + 1]);
            acc[j][0] = bz; acc[j][1] = bz; acc[j][2] = bz; acc[j][3] = bz;
        }
        #pragma unroll
        for (int ic = 0; ic < 3; ic++) {
            float in[6][6];
            #pragma unroll
            for (int r = 0; r < 6; r++)
                #pragma unroll
                for (int c = 0; c < 6; c++)
                    in[r][c] = s_img[ic][iy + r][ix + c];

            #pragma unroll
            for (int ky = 0; ky < 5; ky++) {
                #pragma unroll
                for (int kx = 0; kx < 5; kx++) {
                    const int k = ky * 5 + kx;
                    ull w0 = ld64(&s_wp1[ic][k][0]);
                    ull w1v = ld64(&s_wp1[ic][k][1]);
                    ull w2v = ld64(&s_wp1[ic][k][2]);

                    ull p = pack2(in[ky][kx], in[ky][kx]);
                    acc[0][0] = fma2(w0, p, acc[0][0]);
                    acc[1][0] = fma2(w1v, p, acc[1][0]);
                    acc[2][0] = fma2(w2v, p, acc[2][0]);

                    p = pack2(in[ky][kx+1], in[ky][kx+1]);
                    acc[0][1] = fma2(w0, p, acc[0][1]);
                    acc[1][1] = fma2(w1v, p, acc[1][1]);
                    acc[2][1] = fma2(w2v, p, acc[2][1]);

                    p = pack2(in[ky+1][kx], in[ky+1][kx]);
                    acc[0][2] = fma2(w0, p, acc[0][2]);
                    acc[1][2] = fma2(w1v, p, acc[1][2]);
                    acc[2][2] = fma2(w2v, p, acc[2][2]);

                    p = pack2(in[ky+1][kx+1], in[ky+1][kx+1]);
                    acc[0][3] = fma2(w0, p, acc[0][3]);
                    acc[1][3] = fma2(w1v, p, acc[1][3]);
                    acc[2][3] = fma2(w2v, p, acc[2][3]);
                }
            }
        }
        #pragma unroll
        for (int j = 0; j < 3; j++) {
            float a0l, a0h, a1l, a1h, a2l, a2h, a3l, a3h;
            unpack2(acc[j][0], a0l, a0h);
            unpack2(acc[j][1], a1l, a1h);
            unpack2(acc[j][2], a2l, a2h);
            unpack2(acc[j][3], a3l, a3h);
            float ml = fmaxf(fmaxf(a0l, a1l), fmaxf(a2l, a3l));
            float mh = fmaxf(fmaxf(a0h, a1h), fmaxf(a2h, a3h));
            s_p1[2*j    ][py][px] = fmaxf(ml, 0.0f);
            s_p1[2*j + 1][py][px] = fmaxf(mh, 0.0f);
        }
    }
    __syncthreads();

    if (t < 200) {
        const int pos = t >> 3;
        const int j   = t & 7;
        const int py = pos / 5, px = pos % 5;
        const int iy = 2 * py, ix = 2 * px;

        ull a0, a1, a2, a3;
        {
            ull bz = pack2(s_b2[2*j], s_b2[2*j + 1]);
            a0 = bz; a1 = bz; a2 = bz; a3 = bz;
        }
        #pragma unroll
        for (int ic = 0; ic < 6; ic++) {
            float in[6][6];
            #pragma unroll
            for (int r = 0; r < 6; r++)
                #pragma unroll
                for (int c = 0; c < 6; c++)
                    in[r][c] = s_p1[ic][iy + r][ix + c];

            #pragma unroll
            for (int ky = 0; ky < 5; ky++) {
                #pragma unroll
                for (int kx = 0; kx < 5; kx++) {
                    ull w = ld64(&s_wp2[ic][ky * 5 + kx][j]);
                    a0 = fma2(w, pack2(in[ky  ][kx  ], in[ky  ][kx  ]), a0);
                    a1 = fma2(w, pack2(in[ky  ][kx+1], in[ky  ][kx+1]), a1);
                    a2 = fma2(w, pack2(in[ky+1][kx  ], in[ky+1][kx  ]), a2);
                    a3 = fma2(w, pack2(in[ky+1][kx+1], in[ky+1][kx+1]), a3);
                }
            }
        }
        float a0l,a0h,a1l,a1h,a2l,a2h,a3l,a3h;
        unpack2(a0, a0l, a0h); unpack2(a1, a1l, a1h);
        unpack2(a2, a2l, a2h); unpack2(a3, a3l, a3h);
        float ml = fmaxf(fmaxf(a0l, a1l), fmaxf(a2l, a3l));
        float mh = fmaxf(fmaxf(a0h, a1h), fmaxf(a2h, a3h));
        s_feat[(2*j    ) * 25 + pos] = fmaxf(ml, 0.0f);
        s_feat[(2*j + 1) * 25 + pos] = fmaxf(mh, 0.0f);
    }
    __syncthreads();

    if (b < n_img) {
        float4* dst = reinterpret_cast<float4*>(g_feat + (size_t)b * FEAT);
        const float4* s4 = reinterpret_cast<const float4*>(s_feat);
        for (int i = t; i < 100; i += BDIM) dst[i] = s4[i];
    } else {
        const int slot = b - n_img;
        const int warp = t >> 5, lane = t & 31;
        const float4* f4 = reinterpret_cast<const float4*>(s_feat);
        for (int d = warp; d < HID; d += (BDIM >> 5)) {
            const float4* w4 = reinterpret_cast<const float4*>(Wf + (size_t)d * FEAT);
            float acc = 0.0f;
            #pragma unroll
            for (int it = 0; it < 4; it++) {
                int e = lane + it * 32;
                if (e < 100) {
                    float4 a = f4[e], w = w4[e];
                    acc += a.x*w.x + a.y*w.y + a.z*w.z + a.w*w.w;
                }
            }
            #pragma unroll
            for (int o = 16; o > 0; o >>= 1)
                acc += __shfl_xor_sync(0xFFFFFFFFu, acc, o);
            if (lane == 0) g_rx[(size_t)slot * HID + d] = acc + bf[d];
        }
    }
}

// ---------------------------------------------------------------------------
// Projection kernel: g_grad / g_x for queries. Dual-query f32x2.
// Block: 256 threads (8 warps), PPB query-pairs.
// ---------------------------------------------------------------------------
__global__ __launch_bounds__(256)
void proj_kernel(const float* __restrict__ Wf, const float* __restrict__ bf,
                 const float* __restrict__ Wg, const float* __restrict__ bg,
                 int n)
{
    __shared__ ull s_f2[PPB][FEAT];     // packed (qA, qB) features

    const int t = threadIdx.x;
    const int warp = t >> 5, lane = t & 31;
    const int pbase = blockIdx.x * PPB; // query-pair base

    // load packed features: pair p covers queries 2*(pbase+p), +1
    for (int i = t; i < PPB * 100; i += 256) {
        int p = i / 100, e = i % 100;
        int qA = 2 * (pbase + p);
        float4 va = reinterpret_cast<const float4*>(g_feat + (size_t)qA * FEAT)[e];
        float4 vb = reinterpret_cast<const float4*>(g_feat + (size_t)(qA + 1) * FEAT)[e];
        ull* dst = s_f2[p] + 4 * e;
        dst[0] = pack2(va.x, vb.x);
        dst[1] = pack2(va.y, vb.y);
        dst[2] = pack2(va.z, vb.z);
        dst[3] = pack2(va.w, vb.w);
    }
    __syncthreads();

    for (int d = warp; d < HID * NCLS + HID; d += 8) {
        const float* wrow; float bias;
        if (d < HID * NCLS) { wrow = Wg + (size_t)d * FEAT; bias = bg[d]; }
        else                { wrow = Wf + (size_t)(d - HID*NCLS) * FEAT; bias = bf[d - HID*NCLS]; }
        const float4* w4 = reinterpret_cast<const float4*>(wrow);

        ull acc[PPB];
        #pragma unroll
        for (int p = 0; p < PPB; p++) acc[p] = 0;

        #pragma unroll
        for (int it = 0; it < 4; it++) {
            int e = lane + it * 32;
            if (e < 100) {
                float4 w = w4[e];
                ull wx = pack2(w.x, w.x), wy = pack2(w.y, w.y);
                ull wz = pack2(w.z, w.z), ww = pack2(w.w, w.w);
                #pragma unroll
                for (int p = 0; p < PPB; p++) {
                    const ull* f = s_f2[p] + 4 * e;
                    acc[p] = fma2(f[0], wx, acc[p]);
                    acc[p] = fma2(f[1], wy, acc[p]);
                    acc[p] = fma2(f[2], wz, acc[p]);
                    acc[p] = fma2(f[3], ww, acc[p]);
                }
            }
        }
        #pragma unroll
        for (int p = 0; p < PPB; p++) {
            float sA, sB;
            unpack2(acc[p], sA, sB);
            #pragma unroll
            for (int o = 16; o > 0; o >>= 1) {
                sA += __shfl_xor_sync(0xFFFFFFFFu, sA, o);
                sB += __shfl_xor_sync(0xFFFFFFFFu, sB, o);
            }
            if (lane == 0) {
                int qA = 2 * (pbase + p);
                float vA = sA + bias, vB = sB + bias;
                if (d < HID * NCLS) {
                    g_grad[(size_t)qA * (HID * NCLS) + d]       = vA;
                    g_grad[(size_t)(qA + 1) * (HID * NCLS) + d] = vB;
                } else {
                    int h = d - HID * NCLS;
                    g_x[(size_t)qA * HID + h]       = vA;
                    g_x[(size_t)(qA + 1) * HID + h] = vB;
                }
            }
        }
    }
}

// ---------------------------------------------------------------------------
// Combine kernel: tiny (R3-proven, ~11 us)
// ---------------------------------------------------------------------------
__global__ __launch_bounds__(128)
void combine_kernel(const float* __restrict__ mem,
                    const int*   __restrict__ refs,
                    const float* __restrict__ Wm, const float* __restrict__ bm,
                    float* __restrict__ out, int n, int S)
{
    __shared__ float s_x[QPB][HID];
    __shared__ float s_g[QPB][HID * NCLS];
    __shared__ float s_diff[QPB][SMAX][HID];
    __shared__ float s_norm[QPB][SMAX];
    __shared__ float s_mem[QPB][SMAX][NCLS];
    __shared__ float s_logit[QPB][SMAX][NCLS];
    __shared__ float s_wm[NCLS * NCLS];
    __shared__ float s_bm[NCLS];
    __shared__ int   s_refs[QPB][SMAX];

    const int t = threadIdx.x;
    const int q0 = blockIdx.x * QPB;

    if (t < QPB * SMAX) {
        int ql = t / SMAX, s = t % SMAX;
        s_refs[ql][s] = refs[(size_t)(q0 + ql) * S + s];
    }
    if (t < QPB * HID) {
        int ql = t / HID, h = t % HID;
        s_x[ql][h] = g_x[(size_t)(q0 + ql) * HID + h];
    }
    for (int i = t; i < QPB * HID * NCLS; i += 128) {
        int ql = i / (HID * NCLS), d = i % (HID * NCLS);
        s_g[ql][d] = g_grad[(size_t)(q0 + ql) * (HID * NCLS) + d];
    }
    if (t < NCLS * NCLS) s_wm[t] = Wm[t];
    if (t < NCLS) s_bm[t] = bm[t];
    __syncthreads();

    for (int i = t; i < QPB * SMAX * NCLS; i += 128) {
        int ql = i / (SMAX * NCLS), r2 = i % (SMAX * NCLS);
        int s = r2 / NCLS, c = r2 % NCLS;
        s_mem[ql][s][c] = mem[(size_t)s_refs[ql][s] * NCLS + c];
    }
    if (t < QPB * SMAX) {
        int ql = t / SMAX, s = t % SMAX;
        float acc = 0.0f;
        #pragma unroll
        for (int h = 0; h < HID; h++) {
            float rx = g_rx[(size_t)((q0 + ql) * S + s) * HID + h];
            float dd = s_x[ql][h] - rx;
            s_diff[ql][s][h] = dd;
            acc += dd * dd;
        }
        s_norm[ql][s] = sqrtf(acc);
    }
    __syncthreads();

    for (int i = t; i < QPB * SMAX * NCLS; i += 128) {
        int ql = i / (SMAX * NCLS), r2 = i % (SMAX * NCLS);
        int s = r2 / NCLS, c = r2 % NCLS;
        float acc = s_bm[c];
        #pragma unroll
        for (int jj = 0; jj < NCLS; jj++)
            acc += s_wm[c * NCLS + jj] * s_mem[ql][s][jj];
        #pragma unroll
        for (int h = 0; h < HID; h++)
            acc += s_diff[ql][s][h] * s_g[ql][h * NCLS + c];
        s_logit[ql][s][c] = acc;
    }
    __syncthreads();

    if (t < QPB * NCLS) {
        int ql = t / NCLS, c = t % NCLS;
        float mx = -1e30f;
        for (int s = 0; s < S; s++) mx = fmaxf(mx, -s_norm[ql][s]);
        float se = 0.0f, acc = 0.0f;
        for (int s = 0; s < S; s++) {
            float e = expf(-s_norm[ql][s] - mx);
            se += e;
            acc += e * s_logit[ql][s][c];
        }
        out[(size_t)(q0 + ql) * NCLS + c] = acc / se;
    }
}

// ---------------------------------------------------------------------------
// dummy: pads the per-call launch count to 5 so ncu (-s 5 -c 1) profiles
// lenet_kernel of the first replay instead of a head kernel.
// ---------------------------------------------------------------------------
__global__ void dummy_kernel() {}

// ---------------------------------------------------------------------------
// launcher
// ---------------------------------------------------------------------------
extern "C" void kernel_launch(void* const* d_in, const int* in_sizes, int n_in,
                              void* d_out, int out_size)
{
    const float* img   = (const float*)d_in[0];
    const float* train = (const float*)d_in[1];
    const float* mem   = (const float*)d_in[2];
    const float* w1    = (const float*)d_in[3];
    const float* b1    = (const float*)d_in[4];
    const float* w2    = (const float*)d_in[5];
    const float* b2    = (const float*)d_in[6];
    const float* Wf    = (const float*)d_in[7];
    const float* bf    = (const float*)d_in[8];
    const float* Wg    = (const float*)d_in[9];
    const float* bg    = (const float*)d_in[10];
    const float* Wm    = (const float*)d_in[11];
    const float* bm    = (const float*)d_in[12];
    // d_in[13] = idx : unused by the reference computation
    const int*   refs  = (const int*)d_in[14];

    const int n = in_sizes[0] / (3 * 32 * 32);   // 1024
    const int S = in_sizes[14] / n;              // 8
    if (n > NQ_MAX || S != SMAX || (n % QPB) != 0 || (n % (2 * PPB)) != 0) return;

    const int ntot = n + n * S;                  // 9216
    lenet_kernel<<<ntot, BDIM>>>(img, train, refs, w1, b1, w2, b2, Wf, bf, n);
    proj_kernel<<<n / (2 * PPB), 256>>>(Wf, bf, Wg, bg, n);
    combine_kernel<<<n / QPB, 128>>>(mem, refs, Wm, bm, (float*)d_out, n, S);
    dummy_kernel<<<1, 32>>>();
    dummy_kernel<<<1, 32>>>();
}

// round 12
// speedup vs baseline: 1.0453x; 1.0453x over previous
#include <cuda_runtime.h>
#include <cuda_bf16.h>
#include <math.h>

// ---------------------------------------------------------------------------
// MAD_4612794876398  (round 11)
//  lenet_kernel  : R2 conv core, byte-identical (proven 232 us).
//  proj_kernel   : dual-query f32x2 projection GEMM, 2-D grid
//                  (128 pair-groups x 4 row-chunks = 512 blocks) so the
//                  chip is fully covered (R10's 128-block version = 28 us,
//                  underutilized; this should be ~8 us).
//  combine_kernel: R3-proven tiny combine (~11-13 us).
//  (dummy launches removed — ncu alignment experiment failed, cost 6 us)
// ---------------------------------------------------------------------------

#define FEAT   400
#define HID    12
#define NCLS   10
#define SMAX   8
#define NQ_MAX 1024
#define NR_MAX (NQ_MAX * SMAX)
#define BDIM   224      // lenet block
#define QPB    4        // combine queries per block
#define PPB    4        // proj query-pairs per block (8 queries)
#define NROWS  (HID * NCLS + HID)   // 132 projection rows
#define RCHUNKS 4
#define RPC    33       // rows per chunk (132/4)

__device__ float g_feat[NQ_MAX * FEAT];       // query features
__device__ float g_x[NQ_MAX * HID];           // query Wf projections
__device__ float g_grad[NQ_MAX * HID * NCLS]; // query Wg projections
__device__ float g_rx[NR_MAX * HID];          // ref Wf projections

typedef unsigned long long ull;

__device__ __forceinline__ ull pack2(float lo, float hi) {
    ull r; asm("mov.b64 %0, {%1, %2};" : "=l"(r) : "f"(lo), "f"(hi)); return r;
}
__device__ __forceinline__ void unpack2(ull v, float& lo, float& hi) {
    asm("mov.b64 {%0, %1}, %2;" : "=f"(lo), "=f"(hi) : "l"(v));
}
__device__ __forceinline__ ull fma2(ull a, ull b, ull c) {
    ull d; asm("fma.rn.f32x2 %0, %1, %2, %3;" : "=l"(d) : "l"(a), "l"(b), "l"(c));
    return d;
}
__device__ __forceinline__ ull ld64(const float2* p) {
    return *reinterpret_cast<const ull*>(p);
}

// ---------------------------------------------------------------------------
// LeNet feature kernel: one block per image  (== round 2, unchanged)
// ---------------------------------------------------------------------------
__global__ __launch_bounds__(BDIM, 3)
void lenet_kernel(const float* __restrict__ img,
                  const float* __restrict__ train,
                  const int*   __restrict__ refs,
                  const float* __restrict__ w1, const float* __restrict__ b1,
                  const float* __restrict__ w2, const float* __restrict__ b2,
                  const float* __restrict__ Wf, const float* __restrict__ bf,
                  int n_img)
{
    __shared__ float  s_img[3][32][32];
    __shared__ float2 s_wp1[3][25][3];
    __shared__ float2 s_wp2[6][25][8];
    __shared__ float  s_b1[6];
    __shared__ float  s_b2[16];
    __shared__ float  s_p1[6][14][14];
    __shared__ float  s_feat[FEAT];

    const int b = blockIdx.x;
    const int t = threadIdx.x;

    const float* src = (b < n_img)
        ? img + (size_t)b * 3072
        : train + (size_t)refs[b - n_img] * 3072;

    {
        const float4* s4 = reinterpret_cast<const float4*>(src);
        float4* d4 = reinterpret_cast<float4*>(&s_img[0][0][0]);
        for (int i = t; i < 768; i += BDIM) d4[i] = s4[i];
    }
    for (int i = t; i < 225; i += BDIM) {
        int ic = i / 75, r = i % 75, k = r / 3, j = r % 3;
        s_wp1[ic][k][j] = make_float2(w1[(2*j)     * 75 + ic * 25 + k],
                                      w1[(2*j + 1) * 75 + ic * 25 + k]);
    }
    for (int i = t; i < 1200; i += BDIM) {
        int ic = i / 200, r = i % 200, k = r / 8, j = r % 8;
        s_wp2[ic][k][j] = make_float2(w2[(2*j)     * 150 + ic * 25 + k],
                                      w2[(2*j + 1) * 150 + ic * 25 + k]);
    }
    if (t < 6)  s_b1[t] = b1[t];
    if (t < 16) s_b2[t] = b2[t];
    __syncthreads();

    if (t < 196) {
        const int py = t / 14, px = t % 14;
        const int iy = 2 * py, ix = 2 * px;

        ull acc[3][4];
        #pragma unroll
        for (int j = 0; j < 3; j++) {
            ull bz = pack2(s_b1[2*j], s_b1[2*j + 1]);
            acc[j][0] = bz; acc[j][1] = bz; acc[j][2] = bz; acc[j][3] = bz;
        }
        #pragma unroll
        for (int ic = 0; ic < 3; ic++) {
            float in[6][6];
            #pragma unroll
            for (int r = 0; r < 6; r++)
                #pragma unroll
                for (int c = 0; c < 6; c++)
                    in[r][c] = s_img[ic][iy + r][ix + c];

            #pragma unroll
            for (int ky = 0; ky < 5; ky++) {
                #pragma unroll
                for (int kx = 0; kx < 5; kx++) {
                    const int k = ky * 5 + kx;
                    ull w0 = ld64(&s_wp1[ic][k][0]);
                    ull w1v = ld64(&s_wp1[ic][k][1]);
                    ull w2v = ld64(&s_wp1[ic][k][2]);

                    ull p = pack2(in[ky][kx], in[ky][kx]);
                    acc[0][0] = fma2(w0, p, acc[0][0]);
                    acc[1][0] = fma2(w1v, p, acc[1][0]);
                    acc[2][0] = fma2(w2v, p, acc[2][0]);

                    p = pack2(in[ky][kx+1], in[ky][kx+1]);
                    acc[0][1] = fma2(w0, p, acc[0][1]);
                    acc[1][1] = fma2(w1v, p, acc[1][1]);
                    acc[2][1] = fma2(w2v, p, acc[2][1]);

                    p = pack2(in[ky+1][kx], in[ky+1][kx]);
                    acc[0][2] = fma2(w0, p, acc[0][2]);
                    acc[1][2] = fma2(w1v, p, acc[1][2]);
                    acc[2][2] = fma2(w2v, p, acc[2][2]);

                    p = pack2(in[ky+1][kx+1], in[ky+1][kx+1]);
                    acc[0][3] = fma2(w0, p, acc[0][3]);
                    acc[1][3] = fma2(w1v, p, acc[1][3]);
                    acc[2][3] = fma2(w2v, p, acc[2][3]);
                }
            }
        }
        #pragma unroll
        for (int j = 0; j < 3; j++) {
            float a0l, a0h, a1l, a1h, a2l, a2h, a3l, a3h;
            unpack2(acc[j][0], a0l, a0h);
            unpack2(acc[j][1], a1l, a1h);
            unpack2(acc[j][2], a2l, a2h);
            unpack2(acc[j][3], a3l, a3h);
            float ml = fmaxf(fmaxf(a0l, a1l), fmaxf(a2l, a3l));
            float mh = fmaxf(fmaxf(a0h, a1h), fmaxf(a2h, a3h));
            s_p1[2*j    ][py][px] = fmaxf(ml, 0.0f);
            s_p1[2*j + 1][py][px] = fmaxf(mh, 0.0f);
        }
    }
    __syncthreads();

    if (t < 200) {
        const int pos = t >> 3;
        const int j   = t & 7;
        const int py = pos / 5, px = pos % 5;
        const int iy = 2 * py, ix = 2 * px;

        ull a0, a1, a2, a3;
        {
            ull bz = pack2(s_b2[2*j], s_b2[2*j + 1]);
            a0 = bz; a1 = bz; a2 = bz; a3 = bz;
        }
        #pragma unroll
        for (int ic = 0; ic < 6; ic++) {
            float in[6][6];
            #pragma unroll
            for (int r = 0; r < 6; r++)
                #pragma unroll
                for (int c = 0; c < 6; c++)
                    in[r][c] = s_p1[ic][iy + r][ix + c];

            #pragma unroll
            for (int ky = 0; ky < 5; ky++) {
                #pragma unroll
                for (int kx = 0; kx < 5; kx++) {
                    ull w = ld64(&s_wp2[ic][ky * 5 + kx][j]);
                    a0 = fma2(w, pack2(in[ky  ][kx  ], in[ky  ][kx  ]), a0);
                    a1 = fma2(w, pack2(in[ky  ][kx+1], in[ky  ][kx+1]), a1);
                    a2 = fma2(w, pack2(in[ky+1][kx  ], in[ky+1][kx  ]), a2);
                    a3 = fma2(w, pack2(in[ky+1][kx+1], in[ky+1][kx+1]), a3);
                }
            }
        }
        float a0l,a0h,a1l,a1h,a2l,a2h,a3l,a3h;
        unpack2(a0, a0l, a0h); unpack2(a1, a1l, a1h);
        unpack2(a2, a2l, a2h); unpack2(a3, a3l, a3h);
        float ml = fmaxf(fmaxf(a0l, a1l), fmaxf(a2l, a3l));
        float mh = fmaxf(fmaxf(a0h, a1h), fmaxf(a2h, a3h));
        s_feat[(2*j    ) * 25 + pos] = fmaxf(ml, 0.0f);
        s_feat[(2*j + 1) * 25 + pos] = fmaxf(mh, 0.0f);
    }
    __syncthreads();

    if (b < n_img) {
        float4* dst = reinterpret_cast<float4*>(g_feat + (size_t)b * FEAT);
        const float4* s4 = reinterpret_cast<const float4*>(s_feat);
        for (int i = t; i < 100; i += BDIM) dst[i] = s4[i];
    } else {
        const int slot = b - n_img;
        const int warp = t >> 5, lane = t & 31;
        const float4* f4 = reinterpret_cast<const float4*>(s_feat);
        for (int d = warp; d < HID; d += (BDIM >> 5)) {
            const float4* w4 = reinterpret_cast<const float4*>(Wf + (size_t)d * FEAT);
            float acc = 0.0f;
            #pragma unroll
            for (int it = 0; it < 4; it++) {
                int e = lane + it * 32;
                if (e < 100) {
                    float4 a = f4[e], w = w4[e];
                    acc += a.x*w.x + a.y*w.y + a.z*w.z + a.w*w.w;
                }
            }
            #pragma unroll
            for (int o = 16; o > 0; o >>= 1)
                acc += __shfl_xor_sync(0xFFFFFFFFu, acc, o);
            if (lane == 0) g_rx[(size_t)slot * HID + d] = acc + bf[d];
        }
    }
}

// ---------------------------------------------------------------------------
// Projection kernel: 2-D grid — x: query-pair groups, y: row chunks.
// Each block: 33 rows x 8 packed queries, dual-query f32x2.
// ---------------------------------------------------------------------------
__global__ __launch_bounds__(256)
void proj_kernel(const float* __restrict__ Wf, const float* __restrict__ bf,
                 const float* __restrict__ Wg, const float* __restrict__ bg,
                 int n)
{
    __shared__ ull s_f2[PPB][FEAT];     // packed (qA, qB) features

    const int t = threadIdx.x;
    const int warp = t >> 5, lane = t & 31;
    const int pbase = blockIdx.x * PPB;          // query-pair base
    const int r0 = blockIdx.y * RPC;             // row-chunk start
    const int r1 = r0 + RPC;                     // row-chunk end

    // load packed features: pair p covers queries 2*(pbase+p), +1
    for (int i = t; i < PPB * 100; i += 256) {
        int p = i / 100, e = i % 100;
        int qA = 2 * (pbase + p);
        float4 va = reinterpret_cast<const float4*>(g_feat + (size_t)qA * FEAT)[e];
        float4 vb = reinterpret_cast<const float4*>(g_feat + (size_t)(qA + 1) * FEAT)[e];
        ull* dst = s_f2[p] + 4 * e;
        dst[0] = pack2(va.x, vb.x);
        dst[1] = pack2(va.y, vb.y);
        dst[2] = pack2(va.z, vb.z);
        dst[3] = pack2(va.w, vb.w);
    }
    __syncthreads();

    for (int d = r0 + warp; d < r1; d += 8) {
        const float* wrow; float bias;
        if (d < HID * NCLS) { wrow = Wg + (size_t)d * FEAT; bias = bg[d]; }
        else                { wrow = Wf + (size_t)(d - HID*NCLS) * FEAT; bias = bf[d - HID*NCLS]; }
        const float4* w4 = reinterpret_cast<const float4*>(wrow);

        ull acc[PPB];
        #pragma unroll
        for (int p = 0; p < PPB; p++) acc[p] = 0;

        #pragma unroll
        for (int it = 0; it < 4; it++) {
            int e = lane + it * 32;
            if (e < 100) {
                float4 w = w4[e];
                ull wx = pack2(w.x, w.x), wy = pack2(w.y, w.y);
                ull wz = pack2(w.z, w.z), ww = pack2(w.w, w.w);
                #pragma unroll
                for (int p = 0; p < PPB; p++) {
                    const ull* f = s_f2[p] + 4 * e;
                    acc[p] = fma2(f[0], wx, acc[p]);
                    acc[p] = fma2(f[1], wy, acc[p]);
                    acc[p] = fma2(f[2], wz, acc[p]);
                    acc[p] = fma2(f[3], ww, acc[p]);
                }
            }
        }
        #pragma unroll
        for (int p = 0; p < PPB; p++) {
            float sA, sB;
            unpack2(acc[p], sA, sB);
            #pragma unroll
            for (int o = 16; o > 0; o >>= 1) {
                sA += __shfl_xor_sync(0xFFFFFFFFu, sA, o);
                sB += __shfl_xor_sync(0xFFFFFFFFu, sB, o);
            }
            if (lane == 0) {
                int qA = 2 * (pbase + p);
                float vA = sA + bias, vB = sB + bias;
                if (d < HID * NCLS) {
                    g_grad[(size_t)qA * (HID * NCLS) + d]       = vA;
                    g_grad[(size_t)(qA + 1) * (HID * NCLS) + d] = vB;
                } else {
                    int h = d - HID * NCLS;
                    g_x[(size_t)qA * HID + h]       = vA;
                    g_x[(size_t)(qA + 1) * HID + h] = vB;
                }
            }
        }
    }
}

// ---------------------------------------------------------------------------
// Combine kernel: tiny (R3-proven)
// ---------------------------------------------------------------------------
__global__ __launch_bounds__(128)
void combine_kernel(const float* __restrict__ mem,
                    const int*   __restrict__ refs,
                    const float* __restrict__ Wm, const float* __restrict__ bm,
                    float* __restrict__ out, int n, int S)
{
    __shared__ float s_x[QPB][HID];
    __shared__ float s_g[QPB][HID * NCLS];
    __shared__ float s_diff[QPB][SMAX][HID];
    __shared__ float s_norm[QPB][SMAX];
    __shared__ float s_mem[QPB][SMAX][NCLS];
    __shared__ float s_logit[QPB][SMAX][NCLS];
    __shared__ float s_wm[NCLS * NCLS];
    __shared__ float s_bm[NCLS];
    __shared__ int   s_refs[QPB][SMAX];

    const int t = threadIdx.x;
    const int q0 = blockIdx.x * QPB;

    if (t < QPB * SMAX) {
        int ql = t / SMAX, s = t % SMAX;
        s_refs[ql][s] = refs[(size_t)(q0 + ql) * S + s];
    }
    if (t < QPB * HID) {
        int ql = t / HID, h = t % HID;
        s_x[ql][h] = g_x[(size_t)(q0 + ql) * HID + h];
    }
    for (int i = t; i < QPB * HID * NCLS; i += 128) {
        int ql = i / (HID * NCLS), d = i % (HID * NCLS);
        s_g[ql][d] = g_grad[(size_t)(q0 + ql) * (HID * NCLS) + d];
    }
    if (t < NCLS * NCLS) s_wm[t] = Wm[t];
    if (t < NCLS) s_bm[t] = bm[t];
    __syncthreads();

    for (int i = t; i < QPB * SMAX * NCLS; i += 128) {
        int ql = i / (SMAX * NCLS), r2 = i % (SMAX * NCLS);
        int s = r2 / NCLS, c = r2 % NCLS;
        s_mem[ql][s][c] = mem[(size_t)s_refs[ql][s] * NCLS + c];
    }
    if (t < QPB * SMAX) {
        int ql = t / SMAX, s = t % SMAX;
        float acc = 0.0f;
        #pragma unroll
        for (int h = 0; h < HID; h++) {
            float rx = g_rx[(size_t)((q0 + ql) * S + s) * HID + h];
            float dd = s_x[ql][h] - rx;
            s_diff[ql][s][h] = dd;
            acc += dd * dd;
        }
        s_norm[ql][s] = sqrtf(acc);
    }
    __syncthreads();

    for (int i = t; i < QPB * SMAX * NCLS; i += 128) {
        int ql = i / (SMAX * NCLS), r2 = i % (SMAX * NCLS);
        int s = r2 / NCLS, c = r2 % NCLS;
        float acc = s_bm[c];
        #pragma unroll
        for (int jj = 0; jj < NCLS; jj++)
            acc += s_wm[c * NCLS + jj] * s_mem[ql][s][jj];
        #pragma unroll
        for (int h = 0; h < HID; h++)
            acc += s_diff[ql][s][h] * s_g[ql][h * NCLS + c];
        s_logit[ql][s][c] = acc;
    }
    __syncthreads();

    if (t < QPB * NCLS) {
        int ql = t / NCLS, c = t % NCLS;
        float mx = -1e30f;
        for (int s = 0; s < S; s++) mx = fmaxf(mx, -s_norm[ql][s]);
        float se = 0.0f, acc = 0.0f;
        for (int s = 0; s < S; s++) {
            float e = expf(-s_norm[ql][s] - mx);
            se += e;
            acc += e * s_logit[ql][s][c];
        }
        out[(size_t)(q0 + ql) * NCLS + c] = acc / se;
    }
}

// ---------------------------------------------------------------------------
// launcher
// ---------------------------------------------------------------------------
extern "C" void kernel_launch(void* const* d_in, const int* in_sizes, int n_in,
                              void* d_out, int out_size)
{
    const float* img   = (const float*)d_in[0];
    const float* train = (const float*)d_in[1];
    const float* mem   = (const float*)d_in[2];
    const float* w1    = (const float*)d_in[3];
    const float* b1    = (const float*)d_in[4];
    const float* w2    = (const float*)d_in[5];
    const float* b2    = (const float*)d_in[6];
    const float* Wf    = (const float*)d_in[7];
    const float* bf    = (const float*)d_in[8];
    const float* Wg    = (const float*)d_in[9];
    const float* bg    = (const float*)d_in[10];
    const float* Wm    = (const float*)d_in[11];
    const float* bm    = (const float*)d_in[12];
    // d_in[13] = idx : unused by the reference computation
    const int*   refs  = (const int*)d_in[14];

    const int n = in_sizes[0] / (3 * 32 * 32);   // 1024
    const int S = in_sizes[14] / n;              // 8
    if (n > NQ_MAX || S != SMAX || (n % QPB) != 0 || (n % (2 * PPB)) != 0) return;

    const int ntot = n + n * S;                  // 9216
    lenet_kernel<<<ntot, BDIM>>>(img, train, refs, w1, b1, w2, b2, Wf, bf, n);

    dim3 pgrid(n / (2 * PPB), RCHUNKS);          // 128 x 4 = 512 blocks
    proj_kernel<<<pgrid, 256>>>(Wf, bf, Wg, bg, n);

    combine_kernel<<<n / QPB, 128>>>(mem, refs, Wm, bm, (float*)d_out, n, S);
}